// round 15
// baseline (speedup 1.0000x reference)
#include <cuda_runtime.h>
#include <cuda_fp16.h>
#include <math.h>

#define T 1024
#define H 2048
#define I_DIM 1024
#define E 32

#define BM 64
#define BK 32

// smem layout (bytes), shared shape for both GEMM kernels:
//   stage s (x3, 23552 each): A fp16 64x(32+8pad) = 5120 | raw fp32 weights 18432
//   Bbuf fp16 @70656 (10240) | spair @80896 | total 81152
#define NSTAGE   3
#define STG_SZ   23552
#define RAW_OFF  5120
#define BBUF_OFF 70656
#define SPAIR_OFF 80896
#define DYN_SMEM 81152

// Scratch (no allocations allowed -> __device__ globals)
__device__ int    g_count[E];
__device__ int    g_list[E * 2 * T];
__device__ float  g_pairw[T * 2];
__device__ __align__(16) __half g_xf[(size_t)T * H];           // x in fp16, 4MB
__device__ __align__(16) __half g_hbuf[(size_t)T * 2 * I_DIM]; // h in fp16, 4MB

// ---------------------------------------------------------------------------
__global__ void zero_kernel(float* __restrict__ out) {
    int i = blockIdx.x * blockDim.x + threadIdx.x;
    if (i < T * H) out[i] = 0.0f;
    if (i < E) g_count[i] = 0;
}

__global__ void convert_x_kernel(const float* __restrict__ x) {
    int i = blockIdx.x * blockDim.x + threadIdx.x;
    float2 v = ((const float2*)x)[i];
    ((__half2*)g_xf)[i] = __float22half2_rn(v);
}

// ---------------------------------------------------------------------------
__global__ __launch_bounds__(128) void router_kernel(
    const float* __restrict__ x, const float* __restrict__ gw) {
    int t = blockIdx.x;
    __shared__ float logits[E];
    int warp = threadIdx.x >> 5;
    int lane = threadIdx.x & 31;
    const float4* xt = (const float4*)(x + (size_t)t * H);

    for (int e = warp; e < E; e += 4) {
        const float4* w = (const float4*)(gw + (size_t)e * H);
        float s = 0.0f;
        #pragma unroll 4
        for (int h = lane; h < H / 4; h += 32) {
            float4 a = xt[h];
            float4 b = w[h];
            s += a.x * b.x + a.y * b.y + a.z * b.z + a.w * b.w;
        }
        #pragma unroll
        for (int o = 16; o; o >>= 1) s += __shfl_xor_sync(0xffffffffu, s, o);
        if (lane == 0) logits[e] = s;
    }
    __syncthreads();

    if (threadIdx.x == 0) {
        float b1 = -1e30f, b2 = -1e30f;
        int i1 = 0, i2 = 0;
        #pragma unroll
        for (int e = 0; e < E; e++) {
            float v = logits[e];
            if (v > b1)      { b2 = b1; i2 = i1; b1 = v; i1 = e; }
            else if (v > b2) { b2 = v; i2 = e; }
        }
        float w1 = 1.0f / (1.0f + expf(b2 - b1));
        float w2 = 1.0f - w1;
        g_pairw[t * 2 + 0] = w1;
        g_pairw[t * 2 + 1] = w2;
        int p1 = atomicAdd(&g_count[i1], 1);
        g_list[i1 * 2 * T + p1] = t * 2 + 0;
        int p2 = atomicAdd(&g_count[i2], 1);
        g_list[i2 * 2 * T + p2] = t * 2 + 1;
    }
}

// ---------------------------------------------------------------------------
__device__ __forceinline__ unsigned smem_u32(const void* p) {
    return (unsigned)__cvta_generic_to_shared(p);
}
__device__ __forceinline__ void ldsm_x4(unsigned addr, unsigned (&r)[4]) {
    asm volatile("ldmatrix.sync.aligned.m8n8.x4.shared.b16 {%0,%1,%2,%3}, [%4];\n"
        : "=r"(r[0]), "=r"(r[1]), "=r"(r[2]), "=r"(r[3]) : "r"(addr));
}
__device__ __forceinline__ void mma16816(float (&c)[4], const unsigned (&a)[4],
                                         unsigned b0, unsigned b1) {
    asm volatile(
        "mma.sync.aligned.m16n8k16.row.col.f32.f16.f16.f32 "
        "{%0,%1,%2,%3}, {%4,%5,%6,%7}, {%8,%9}, {%0,%1,%2,%3};\n"
        : "+f"(c[0]), "+f"(c[1]), "+f"(c[2]), "+f"(c[3])
        : "r"(a[0]), "r"(a[1]), "r"(a[2]), "r"(a[3]), "r"(b0), "r"(b1));
}
__device__ __forceinline__ uint2 cvt4(float4 v) {
    __half2 h0 = __float22half2_rn(make_float2(v.x, v.y));
    __half2 h1 = __float22half2_rn(make_float2(v.z, v.w));
    uint2 r;
    r.x = *reinterpret_cast<unsigned*>(&h0);
    r.y = *reinterpret_cast<unsigned*>(&h1);
    return r;
}
__device__ __forceinline__ void cp_async16(unsigned dst, const void* src) {
    asm volatile("cp.async.cg.shared.global [%0], [%1], 16;\n" :: "r"(dst), "l"(src));
}
#define CP_COMMIT() asm volatile("cp.async.commit_group;\n" ::: "memory")
#define CP_WAIT(n)  asm volatile("cp.async.wait_group %0;\n" :: "n"(n) : "memory")

// ---------------------------------------------------------------------------
// Gate+Up: M=64 slots x N=64 i-cols (G and U), K=H. 3-stage cp.async pipeline.
__global__ __launch_bounds__(256) void gateup_kernel(
    const float* __restrict__ Wg, const float* __restrict__ Wu) {
    extern __shared__ char ds[];
    int e = blockIdx.z;
    int cnt = g_count[e];
    int slot0 = blockIdx.x * BM;
    if (slot0 >= cnt) return;
    int i0 = blockIdx.y * 64;

    int tid = threadIdx.x;
    int* spair = (int*)(ds + SPAIR_OFF);
    if (tid < BM) {
        int s = slot0 + tid;
        spair[tid] = (s < cnt) ? g_list[e * 2 * T + s] : g_list[e * 2 * T];
    }
    __syncthreads();
    unsigned sb = smem_u32(ds);

    // A cp.async: row = tid>>2 (64 rows of 64B), chunk = tid&3
    int arow = tid >> 2, achk = tid & 3;
    const char* srcA = (const char*)(g_xf + (size_t)(spair[arow] >> 1) * H) + achk * 16;
    unsigned dstA = arow * 80 + achk * 16;
    // weights: matrix = tid>>7 (0=G,1=U), row = (tid>>1)&63, half = tid&1 (64B each)
    int wsel = tid >> 7, wrow = (tid >> 1) & 63, whalf = tid & 1;
    const float* Wm = wsel ? Wu : Wg;
    const char* srcW = (const char*)(Wm + ((size_t)e * I_DIM + i0 + wrow) * H) + whalf * 64;
    unsigned rawoff = RAW_OFF + wsel * 9216 + wrow * 144 + whalf * 64;

    int warp = tid >> 5, lane = tid & 31;
    int wm = warp >> 2;   // 0..1 (32 rows each)
    int wn = warp & 3;    // 0..3 (16 cols each)
    unsigned aoff0 = ((wm * 32 + (lane & 15)) * 40 + (lane >> 4) * 8) * 2;
    unsigned aoff1 = aoff0 + 16 * 80;
    unsigned boff = ((wn * 16 + (lane & 7) + ((lane >> 4) & 1) * 8) * 40
                     + ((lane >> 3) & 1) * 8) * 2;

    float cg[2][2][4] = {};
    float cu[2][2][4] = {};

    auto fill = [&](int t) {
        unsigned st = sb + (t % NSTAGE) * STG_SZ;
        size_t kA = (size_t)t * 64;     // BK halves = 64B
        size_t kW = (size_t)t * 128;    // BK floats = 128B
        cp_async16(st + dstA, srcA + kA);
        #pragma unroll
        for (int j = 0; j < 4; j++)
            cp_async16(st + rawoff + j * 16, srcW + kW + j * 16);
        CP_COMMIT();
    };
    fill(0);
    fill(1);

    const int NIT = H / BK;   // 64
    for (int t = 0; t < NIT; t++) {
        int s = t % NSTAGE;
        __syncthreads();   // MMA(t-1) done with stage (t-1)%3 and Bbuf
        if (t + 2 < NIT) { fill(t + 2); CP_WAIT(2); }
        else if (t + 1 < NIT) { CP_WAIT(1); }
        else { CP_WAIT(0); }

        // convert own staged 16 floats -> fp16 Bbuf (ldsm layout, pitch 40)
        {
            const float* rw = (const float*)(ds + s * STG_SZ + RAW_OFF
                                             + wsel * 9216 + wrow * 144 + whalf * 64);
            __half* bb = (__half*)(ds + BBUF_OFF + wsel * 5120);
            #pragma unroll
            for (int j = 0; j < 2; j++) {
                float4 v0 = *(const float4*)(rw + j * 8);
                float4 v1 = *(const float4*)(rw + j * 8 + 4);
                uint2 p0 = cvt4(v0);
                uint2 p1 = cvt4(v1);
                *(uint2*)(bb + wrow * 40 + whalf * 16 + j * 8)     = p0;
                *(uint2*)(bb + wrow * 40 + whalf * 16 + j * 8 + 4) = p1;
            }
        }
        __syncthreads();

        unsigned st = sb + s * STG_SZ;
        #pragma unroll
        for (int ks = 0; ks < 2; ks++) {
            unsigned kb = ks * 32;
            unsigned ah0[4], ah1[4];
            ldsm_x4(st + aoff0 + kb, ah0);
            ldsm_x4(st + aoff1 + kb, ah1);
            unsigned bg[4], bu[4];
            ldsm_x4(sb + BBUF_OFF + boff + kb, bg);
            ldsm_x4(sb + BBUF_OFF + 5120 + boff + kb, bu);

            mma16816(cg[0][0], ah0, bg[0], bg[1]);
            mma16816(cg[0][1], ah0, bg[2], bg[3]);
            mma16816(cg[1][0], ah1, bg[0], bg[1]);
            mma16816(cg[1][1], ah1, bg[2], bg[3]);
            mma16816(cu[0][0], ah0, bu[0], bu[1]);
            mma16816(cu[0][1], ah0, bu[2], bu[3]);
            mma16816(cu[1][0], ah1, bu[0], bu[1]);
            mma16816(cu[1][1], ah1, bu[2], bu[3]);
        }
    }

    // epilogue: h = silu(g) * u * combine_weight -> g_hbuf (fp16)
    #pragma unroll
    for (int mi = 0; mi < 2; mi++) {
        #pragma unroll
        for (int half = 0; half < 2; half++) {
            int row = wm * 32 + mi * 16 + (lane >> 2) + half * 8;
            if (slot0 + row < cnt) {
                int pair = spair[row];
                float w = g_pairw[pair];
                #pragma unroll
                for (int ni = 0; ni < 2; ni++) {
                    int col = i0 + wn * 16 + ni * 8 + ((lane & 3) << 1);
                    float g0 = cg[mi][ni][half * 2 + 0];
                    float g1 = cg[mi][ni][half * 2 + 1];
                    float u0 = cu[mi][ni][half * 2 + 0];
                    float u1 = cu[mi][ni][half * 2 + 1];
                    float h0 = g0 / (1.0f + expf(-g0)) * u0 * w;
                    float h1 = g1 / (1.0f + expf(-g1)) * u1 * w;
                    *(__half2*)(g_hbuf + (size_t)pair * I_DIM + col) =
                        __floats2half2_rn(h0, h1);
                }
            }
        }
    }
}

// ---------------------------------------------------------------------------
// Down: M=64 slots x N=128 h-cols, K=I. Same 3-stage pipeline. Scatter-add.
__global__ __launch_bounds__(256) void down_kernel(
    const float* __restrict__ Wd, float* __restrict__ out) {
    extern __shared__ char ds[];
    int e = blockIdx.z;
    int cnt = g_count[e];
    int slot0 = blockIdx.x * BM;
    if (slot0 >= cnt) return;
    int h0 = blockIdx.y * 128;

    int tid = threadIdx.x;
    int* spair = (int*)(ds + SPAIR_OFF);
    if (tid < BM) {
        int s = slot0 + tid;
        spair[tid] = (s < cnt) ? g_list[e * 2 * T + s] : g_list[e * 2 * T];
    }
    __syncthreads();
    unsigned sb = smem_u32(ds);

    int arow = tid >> 2, achk = tid & 3;
    const char* srcA = (const char*)(g_hbuf + (size_t)spair[arow] * I_DIM) + achk * 16;
    unsigned dstA = arow * 80 + achk * 16;
    // weights: 128 rows, row = tid>>1, half = tid&1 (64B each)
    int wrow = tid >> 1, whalf = tid & 1;
    const char* srcW = (const char*)(Wd + ((size_t)e * H + h0 + wrow) * I_DIM) + whalf * 64;
    unsigned rawoff = RAW_OFF + wrow * 144 + whalf * 64;

    int warp = tid >> 5, lane = tid & 31;
    int wm = warp >> 2;   // 0..1
    int wn = warp & 3;    // 0..3 (32 cols each)
    unsigned aoff0 = ((wm * 32 + (lane & 15)) * 40 + (lane >> 4) * 8) * 2;
    unsigned aoff1 = aoff0 + 16 * 80;
    unsigned boffbase = ((wn * 32 + (lane & 7) + ((lane >> 4) & 1) * 8) * 40
                         + ((lane >> 3) & 1) * 8) * 2;

    float c[2][4][4] = {};

    auto fill = [&](int t) {
        unsigned st = sb + (t % NSTAGE) * STG_SZ;
        size_t kA = (size_t)t * 64;
        size_t kW = (size_t)t * 128;
        cp_async16(st + dstA, srcA + kA);
        #pragma unroll
        for (int j = 0; j < 4; j++)
            cp_async16(st + rawoff + j * 16, srcW + kW + j * 16);
        CP_COMMIT();
    };
    fill(0);
    fill(1);

    const int NIT = I_DIM / BK;   // 32
    for (int t = 0; t < NIT; t++) {
        int s = t % NSTAGE;
        __syncthreads();
        if (t + 2 < NIT) { fill(t + 2); CP_WAIT(2); }
        else if (t + 1 < NIT) { CP_WAIT(1); }
        else { CP_WAIT(0); }

        {
            const float* rw = (const float*)(ds + s * STG_SZ + RAW_OFF
                                             + wrow * 144 + whalf * 64);
            __half* bb = (__half*)(ds + BBUF_OFF);
            #pragma unroll
            for (int j = 0; j < 2; j++) {
                float4 v0 = *(const float4*)(rw + j * 8);
                float4 v1 = *(const float4*)(rw + j * 8 + 4);
                uint2 p0 = cvt4(v0);
                uint2 p1 = cvt4(v1);
                *(uint2*)(bb + wrow * 40 + whalf * 16 + j * 8)     = p0;
                *(uint2*)(bb + wrow * 40 + whalf * 16 + j * 8 + 4) = p1;
            }
        }
        __syncthreads();

        unsigned st = sb + s * STG_SZ;
        #pragma unroll
        for (int ks = 0; ks < 2; ks++) {
            unsigned kb = ks * 32;
            unsigned ah0[4], ah1[4];
            ldsm_x4(st + aoff0 + kb, ah0);
            ldsm_x4(st + aoff1 + kb, ah1);
            unsigned bh0[4], bh1[4];
            ldsm_x4(sb + BBUF_OFF + boffbase + kb, bh0);
            ldsm_x4(sb + BBUF_OFF + 16 * 80 + boffbase + kb, bh1);

            #pragma unroll
            for (int mi = 0; mi < 2; mi++) {
                const unsigned (&ah)[4] = mi ? ah1 : ah0;
                mma16816(c[mi][0], ah, bh0[0], bh0[1]);
                mma16816(c[mi][1], ah, bh0[2], bh0[3]);
                mma16816(c[mi][2], ah, bh1[0], bh1[1]);
                mma16816(c[mi][3], ah, bh1[2], bh1[3]);
            }
        }
    }

    // epilogue: scatter-add into out[token][h]
    #pragma unroll
    for (int mi = 0; mi < 2; mi++) {
        #pragma unroll
        for (int half = 0; half < 2; half++) {
            int row = wm * 32 + mi * 16 + (lane >> 2) + half * 8;
            if (slot0 + row < cnt) {
                int token = spair[row] >> 1;
                float* orow = out + (size_t)token * H + h0 + wn * 32;
                #pragma unroll
                for (int ni = 0; ni < 4; ni++) {
                    int col = ni * 8 + ((lane & 3) << 1);
                    atomicAdd(&orow[col],     c[mi][ni][half * 2 + 0]);
                    atomicAdd(&orow[col + 1], c[mi][ni][half * 2 + 1]);
                }
            }
        }
    }
}

// ---------------------------------------------------------------------------
extern "C" void kernel_launch(void* const* d_in, const int* in_sizes, int n_in,
                              void* d_out, int out_size) {
    const float* x  = (const float*)d_in[0];
    const float* gw = (const float*)d_in[1];
    const float* Wg = (const float*)d_in[2];
    const float* Wu = (const float*)d_in[3];
    const float* Wd = (const float*)d_in[4];
    float* out = (float*)d_out;

    cudaFuncSetAttribute(gateup_kernel,
        cudaFuncAttributeMaxDynamicSharedMemorySize, DYN_SMEM);
    cudaFuncSetAttribute(down_kernel,
        cudaFuncAttributeMaxDynamicSharedMemorySize, DYN_SMEM);

    zero_kernel<<<(T * H + 255) / 256, 256>>>(out);
    convert_x_kernel<<<(T * H / 2) / 256, 256>>>(x);
    router_kernel<<<T, 128>>>(x, gw);
    {
        dim3 grid(T * 2 / BM, I_DIM / 64, E);
        gateup_kernel<<<grid, 256, DYN_SMEM>>>(Wg, Wu);
    }
    {
        dim3 grid(T * 2 / BM, H / 128, E);
        down_kernel<<<grid, 256, DYN_SMEM>>>(Wd, out);
    }
}